// round 4
// baseline (speedup 1.0000x reference)
#include <cuda_runtime.h>
#include <cuda_bf16.h>

#define NUM_NODES 10000
#define N_EDGES   640000
#define D         128
#define BUCKET    128
#define OVF_MAX   4096

// ---------------- device scratch ----------------
__device__ float d_S[NUM_NODES * D];
__device__ float d_A[NUM_NODES * D];
__device__ int   d_cur[NUM_NODES];
__device__ float d_degf[NUM_NODES];
__device__ int2  d_perm2[NUM_NODES * BUCKET];
__device__ int3  d_ovf[OVF_MAX];
__device__ int   d_ovf_cnt;
__device__ float d_Mf[512 * D];
__device__ float d_cvec[D];
__device__ int   d_is64;

// ---------------- helpers ----------------
__device__ __forceinline__ int load_idx(const void* ei, int which, int e, int is64) {
    if (is64) {
        const long long* p = (const long long*)ei;
        return (int)__ldg(p + (size_t)which * N_EDGES + e);
    } else {
        const int* p = (const int*)ei;
        return __ldg(p + (size_t)which * N_EDGES + e);
    }
}
__device__ __forceinline__ float4 ldg4(const float* p)  { return __ldg((const float4*)p); }
__device__ __forceinline__ float4 ldcs4(const float* p) { return __ldcs((const float4*)p); }

// ---------------- K0: setup = weight fusion + dtype probe + counter zeroing ----------------
// blocks [0,512):   fuse weights into Mf / cvec
// block  512:       dtype probe + ovf reset
// blocks [513,592): zero d_cur
__global__ void k_setup(const float* __restrict__ W1,
                        const float* __restrict__ b1,
                        const float* __restrict__ W2,
                        const int*   __restrict__ ei_words) {
    int r = blockIdx.x, o = threadIdx.x;   // 128 threads
    if (r >= 512) {
        if (r == 512) {
            int w = ei_words[2 * o + 1];   // high words if int64
            int any = __syncthreads_or(w != 0);
            if (o == 0) { d_is64 = (any == 0) ? 1 : 0; d_ovf_cnt = 0; }
        } else {
            int i = (r - 513) * 128 + o;
            if (i < NUM_NODES) d_cur[i] = 0;
        }
        return;
    }
    __shared__ float row[D];
    if (r >= 256 && r < 384) {
        d_Mf[r * D + o] = W2[(128 + (r - 256)) * D + o];
        return;
    }
    int w1row = (r < 128) ? r : (r < 256) ? (256 + (r - 128)) : (128 + (r - 384));
    row[o] = W1[w1row * D + o];
    __syncthreads();
    float acc = 0.f;
#pragma unroll 8
    for (int h = 0; h < D; h++) acc += row[h] * __ldg(W2 + h * D + o);
    d_Mf[r * D + o] = acc;
    if (r == 0) {
        __syncthreads();
        row[o] = b1[o];
        __syncthreads();
        float c = 0.f;
#pragma unroll 8
        for (int h = 0; h < D; h++) c += row[h] * __ldg(W2 + h * D + o);
        d_cvec[o] = c;
    }
}

// ---------------- K1: single-pass bucket scatter ----------------
__global__ void k_scatter(const void* ei) {
    int is64 = d_is64;
    int e = blockIdx.x * blockDim.x + threadIdx.x;
    if (e >= N_EDGES) return;
    int dst = load_idx(ei, 1, e, is64);
    int src = load_idx(ei, 0, e, is64);
    int pos = atomicAdd(&d_cur[dst], 1);
    if (pos < BUCKET) {
        d_perm2[(dst << 7) + pos] = make_int2(e, src);
    } else {
        int o = atomicAdd(&d_ovf_cnt, 1);
        if (o < OVF_MAX) d_ovf[o] = make_int3(dst, e, src);
    }
}

// ---------------- K2: atomic-free segment sums (warp per node, unroll 8) ----------------
__global__ void __launch_bounds__(256, 4)
k_agg(const float* __restrict__ x, const float* __restrict__ ea) {
    int n = blockIdx.x * 8 + (threadIdx.x >> 5);
    if (n >= NUM_NODES) return;
    int lane = threadIdx.x & 31;
    int deg = d_cur[n];
    if (lane == 0) d_degf[n] = (float)deg;
    int cnt = min(deg, BUCKET);
    const int2* bucket = d_perm2 + ((size_t)n << 7);

    float4 aS = make_float4(0.f, 0.f, 0.f, 0.f);
    float4 aA = make_float4(0.f, 0.f, 0.f, 0.f);

    int j = 0;
    for (; j + 8 <= cnt; j += 8) {
        int2 p[8];
#pragma unroll
        for (int v = 0; v < 8; v++) p[v] = __ldg(bucket + j + v);
        float4 xv[8], av[8];
#pragma unroll
        for (int v = 0; v < 8; v++) xv[v] = ldg4(x + (size_t)p[v].y * D + lane * 4);
#pragma unroll
        for (int v = 0; v < 8; v++) av[v] = ldcs4(ea + (size_t)p[v].x * D + lane * 4);
#pragma unroll
        for (int v = 0; v < 8; v++) {
            aS.x += xv[v].x; aS.y += xv[v].y; aS.z += xv[v].z; aS.w += xv[v].w;
            aA.x += av[v].x; aA.y += av[v].y; aA.z += av[v].z; aA.w += av[v].w;
        }
    }
    for (; j < cnt; j++) {
        int2 p = __ldg(bucket + j);
        float4 xv = ldg4(x + (size_t)p.y * D + lane * 4);
        float4 av = ldcs4(ea + (size_t)p.x * D + lane * 4);
        aS.x += xv.x; aS.y += xv.y; aS.z += xv.z; aS.w += xv.w;
        aA.x += av.x; aA.y += av.y; aA.z += av.z; aA.w += av.w;
    }
    *(float4*)(d_S + (size_t)n * D + lane * 4) = aS;
    *(float4*)(d_A + (size_t)n * D + lane * 4) = aA;
}

// ---------------- K3: exact fixup for bucket overflow ----------------
__global__ void k_ovf(const float* __restrict__ x, const float* __restrict__ ea) {
    int cnt = d_ovf_cnt;
    if (cnt > OVF_MAX) cnt = OVF_MAX;
    int lane = threadIdx.x;
    for (int i = blockIdx.x; i < cnt; i += gridDim.x) {
        int3 v = d_ovf[i];
        atomicAdd(&d_S[(size_t)v.x * D + lane], __ldg(x  + (size_t)v.z * D + lane));
        atomicAdd(&d_A[(size_t)v.x * D + lane], __ldg(ea + (size_t)v.y * D + lane));
    }
}

// ---------------- K4: fused node GEMM, 32-node tiles ----------------
// out = [S | A | x | deg*x] @ Mf + deg (x) cvec + b2
// 32 nodes x 128 outs, 256 threads, 2 nodes x 8 outs per thread (plain FFMA)
__global__ void __launch_bounds__(256)
k_gemm(const float* __restrict__ x,
       const float* __restrict__ b2,
       float* __restrict__ out) {
    __shared__ float Us[32 * 33];
    __shared__ float Ms[32 * 128];
    int t = threadIdx.x;
    int n0 = blockIdx.x * 32;
    int og = t & 15;          // 8 outputs
    int ng = t >> 4;          // 2 nodes

    float acc[2][8];
#pragma unroll
    for (int i = 0; i < 2; i++)
#pragma unroll
        for (int jj = 0; jj < 8; jj++) acc[i][jj] = 0.f;

    for (int k0 = 0; k0 < 512; k0 += 32) {
        int region = k0 >> 7;
        int kloc = k0 & 127;
        const float* base = (region == 0) ? d_S : (region == 1) ? d_A : x;

        // U tile: 32x32 floats, 1 float4 per thread
        {
            int r = t >> 3, c = (t & 7) * 4;
            int n = n0 + r;
            float4 val = make_float4(0.f, 0.f, 0.f, 0.f);
            if (n < NUM_NODES) {
                val = ldg4(base + (size_t)n * D + kloc + c);
                if (region == 3) {
                    float dg = d_degf[n];
                    val.x *= dg; val.y *= dg; val.z *= dg; val.w *= dg;
                }
            }
            Us[r * 33 + c + 0] = val.x;
            Us[r * 33 + c + 1] = val.y;
            Us[r * 33 + c + 2] = val.z;
            Us[r * 33 + c + 3] = val.w;
        }
        // M tile: 32x128 floats, 4 float4 per thread
#pragma unroll
        for (int v = 0; v < 4; v++) {
            int id = t * 16 + v * 4;
            int r = id >> 7, c = id & 127;
            *(float4*)(Ms + r * 128 + c) = ldg4(d_Mf + (size_t)(k0 + r) * 128 + c);
        }
        __syncthreads();

#pragma unroll
        for (int kk = 0; kk < 32; kk++) {
            float u0 = Us[(ng * 2 + 0) * 33 + kk];
            float u1 = Us[(ng * 2 + 1) * 33 + kk];
            float4 m0 = *(float4*)(Ms + kk * 128 + og * 8);
            float4 m1 = *(float4*)(Ms + kk * 128 + og * 8 + 4);
            float m[8] = {m0.x, m0.y, m0.z, m0.w, m1.x, m1.y, m1.z, m1.w};
#pragma unroll
            for (int jj = 0; jj < 8; jj++) {
                acc[0][jj] += u0 * m[jj];
                acc[1][jj] += u1 * m[jj];
            }
        }
        __syncthreads();
    }

    // epilogue
#pragma unroll
    for (int i = 0; i < 2; i++) {
        int n = n0 + ng * 2 + i;
        if (n >= NUM_NODES) continue;
        float dg = d_degf[n];
        float o8[8];
#pragma unroll
        for (int jj = 0; jj < 8; jj++) {
            int o = og * 8 + jj;
            o8[jj] = acc[i][jj] + dg * d_cvec[o] + b2[o];
        }
        float4* outp = (float4*)(out + (size_t)n * D + og * 8);
        outp[0] = make_float4(o8[0], o8[1], o8[2], o8[3]);
        outp[1] = make_float4(o8[4], o8[5], o8[6], o8[7]);
    }
}

// ---------------- launch ----------------
extern "C" void kernel_launch(void* const* d_in, const int* in_sizes, int n_in,
                              void* d_out, int out_size) {
    const float* x  = (const float*)d_in[0];
    const void*  ei = d_in[1];
    const float* ea = (const float*)d_in[2];
    const float* W1 = (const float*)d_in[3];
    const float* b1 = (const float*)d_in[4];
    const float* W2 = (const float*)d_in[5];
    const float* b2 = (const float*)d_in[6];
    float* out = (float*)d_out;

    k_setup<<<592, 128>>>(W1, b1, W2, (const int*)ei);
    k_scatter<<<(N_EDGES + 255) / 256, 256>>>(ei);
    k_agg<<<(NUM_NODES + 7) / 8, 256>>>(x, ea);
    k_ovf<<<4, 128>>>(x, ea);
    k_gemm<<<(NUM_NODES + 31) / 32, 256>>>(x, b2, out);
}

// round 5
// speedup vs baseline: 1.2746x; 1.2746x over previous
#include <cuda_runtime.h>
#include <cuda_bf16.h>

#define NUM_NODES 10000
#define N_EDGES   640000
#define D         128
#define BUCKET    128
#define OVF_MAX   4096

// ---------------- device scratch ----------------
__device__ float d_S[NUM_NODES * D];
__device__ float d_A[NUM_NODES * D];
__device__ int   d_cur[NUM_NODES];
__device__ float d_degf[NUM_NODES];
__device__ int2  d_perm2[NUM_NODES * BUCKET];
__device__ int3  d_ovf[OVF_MAX];
__device__ int   d_ovf_cnt;
__device__ float d_Mf[512 * D];
__device__ float d_cvec[D];
__device__ int   d_is64;

// ---------------- helpers ----------------
__device__ __forceinline__ int load_idx(const void* ei, int which, int e, int is64) {
    if (is64) {
        const long long* p = (const long long*)ei;
        return (int)__ldg(p + (size_t)which * N_EDGES + e);
    } else {
        const int* p = (const int*)ei;
        return __ldg(p + (size_t)which * N_EDGES + e);
    }
}
__device__ __forceinline__ float4 ldg4(const float* p)  { return __ldg((const float4*)p); }
__device__ __forceinline__ float4 ldcs4(const float* p) { return __ldcs((const float4*)p); }

// ---------------- K0: setup = weight fusion + dtype probe + counter zeroing ----------------
__global__ void k_setup(const float* __restrict__ W1,
                        const float* __restrict__ b1,
                        const float* __restrict__ W2,
                        const int*   __restrict__ ei_words) {
    int r = blockIdx.x, o = threadIdx.x;   // 128 threads
    if (r >= 512) {
        if (r == 512) {
            int w = ei_words[2 * o + 1];   // high words if int64
            int any = __syncthreads_or(w != 0);
            if (o == 0) { d_is64 = (any == 0) ? 1 : 0; d_ovf_cnt = 0; }
        } else {
            int i = (r - 513) * 128 + o;
            if (i < NUM_NODES) d_cur[i] = 0;
        }
        return;
    }
    __shared__ float row[D];
    if (r >= 256 && r < 384) {
        d_Mf[r * D + o] = W2[(128 + (r - 256)) * D + o];
        return;
    }
    int w1row = (r < 128) ? r : (r < 256) ? (256 + (r - 128)) : (128 + (r - 384));
    row[o] = W1[w1row * D + o];
    __syncthreads();
    float acc = 0.f;
#pragma unroll 8
    for (int h = 0; h < D; h++) acc += row[h] * __ldg(W2 + h * D + o);
    d_Mf[r * D + o] = acc;
    if (r == 0) {
        __syncthreads();
        row[o] = b1[o];
        __syncthreads();
        float c = 0.f;
#pragma unroll 8
        for (int h = 0; h < D; h++) c += row[h] * __ldg(W2 + h * D + o);
        d_cvec[o] = c;
    }
}

// ---------------- K1: single-pass bucket scatter ----------------
__global__ void k_scatter(const void* ei) {
    int is64 = d_is64;
    int e = blockIdx.x * blockDim.x + threadIdx.x;
    if (e >= N_EDGES) return;
    int dst = load_idx(ei, 1, e, is64);
    int src = load_idx(ei, 0, e, is64);
    int pos = atomicAdd(&d_cur[dst], 1);
    if (pos < BUCKET) {
        d_perm2[(dst << 7) + pos] = make_int2(e, src);
    } else {
        int o = atomicAdd(&d_ovf_cnt, 1);
        if (o < OVF_MAX) d_ovf[o] = make_int3(dst, e, src);
    }
}

// ---------------- K2: atomic-free segment sums (warp per node, unroll 4 = R3 hot loop) ----------------
// 128 threads / 4 nodes per block for finer load balancing; inline overflow fixup.
__global__ void k_agg(const float* __restrict__ x, const float* __restrict__ ea) {
    int n = blockIdx.x * 4 + (threadIdx.x >> 5);
    if (n >= NUM_NODES) return;
    int lane = threadIdx.x & 31;
    int deg = d_cur[n];
    if (lane == 0) d_degf[n] = (float)deg;
    int cnt = min(deg, BUCKET);
    const int2* bucket = d_perm2 + ((size_t)n << 7);

    float4 aS = make_float4(0.f, 0.f, 0.f, 0.f);
    float4 aA = make_float4(0.f, 0.f, 0.f, 0.f);

    int j = 0;
    for (; j + 4 <= cnt; j += 4) {
        int2 p0 = __ldg(bucket + j + 0);
        int2 p1 = __ldg(bucket + j + 1);
        int2 p2 = __ldg(bucket + j + 2);
        int2 p3 = __ldg(bucket + j + 3);
        float4 x0 = ldg4(x + (size_t)p0.y * D + lane * 4);
        float4 x1 = ldg4(x + (size_t)p1.y * D + lane * 4);
        float4 x2 = ldg4(x + (size_t)p2.y * D + lane * 4);
        float4 x3 = ldg4(x + (size_t)p3.y * D + lane * 4);
        float4 a0 = ldcs4(ea + (size_t)p0.x * D + lane * 4);
        float4 a1 = ldcs4(ea + (size_t)p1.x * D + lane * 4);
        float4 a2 = ldcs4(ea + (size_t)p2.x * D + lane * 4);
        float4 a3 = ldcs4(ea + (size_t)p3.x * D + lane * 4);
        aS.x += (x0.x + x1.x) + (x2.x + x3.x);
        aS.y += (x0.y + x1.y) + (x2.y + x3.y);
        aS.z += (x0.z + x1.z) + (x2.z + x3.z);
        aS.w += (x0.w + x1.w) + (x2.w + x3.w);
        aA.x += (a0.x + a1.x) + (a2.x + a3.x);
        aA.y += (a0.y + a1.y) + (a2.y + a3.y);
        aA.z += (a0.z + a1.z) + (a2.z + a3.z);
        aA.w += (a0.w + a1.w) + (a2.w + a3.w);
    }
    for (; j < cnt; j++) {
        int2 p = __ldg(bucket + j);
        float4 xv = ldg4(x + (size_t)p.y * D + lane * 4);
        float4 av = ldcs4(ea + (size_t)p.x * D + lane * 4);
        aS.x += xv.x; aS.y += xv.y; aS.z += xv.z; aS.w += xv.w;
        aA.x += av.x; aA.y += av.y; aA.z += av.z; aA.w += av.w;
    }

    // inline overflow fixup (deg > BUCKET essentially never happens)
    if (deg > BUCKET) {
        int cnt_o = d_ovf_cnt;
        if (cnt_o > OVF_MAX) cnt_o = OVF_MAX;
        for (int i = 0; i < cnt_o; i++) {
            int3 v = d_ovf[i];   // (dst, e, src)
            if (v.x == n) {
                float4 xv = ldg4(x + (size_t)v.z * D + lane * 4);
                float4 av = ldg4(ea + (size_t)v.y * D + lane * 4);
                aS.x += xv.x; aS.y += xv.y; aS.z += xv.z; aS.w += xv.w;
                aA.x += av.x; aA.y += av.y; aA.z += av.z; aA.w += av.w;
            }
        }
    }

    *(float4*)(d_S + (size_t)n * D + lane * 4) = aS;
    *(float4*)(d_A + (size_t)n * D + lane * 4) = aA;
}

// ---------------- K3: fused node GEMM (R3 known-good 64-node tile) ----------------
// out = [S | A | x | deg*x] @ Mf + deg (x) cvec + b2
__global__ void k_gemm(const float* __restrict__ x,
                       const float* __restrict__ b2,
                       float* __restrict__ out) {
    __shared__ float Us[64 * 33];
    __shared__ float Ms[32 * 128];
    int t = threadIdx.x;
    int n0 = blockIdx.x * 64;
    int og = t & 15;
    int ng = t >> 4;

    float acc[4][8];
#pragma unroll
    for (int i = 0; i < 4; i++)
#pragma unroll
        for (int jj = 0; jj < 8; jj++) acc[i][jj] = 0.f;

    for (int k0 = 0; k0 < 512; k0 += 32) {
        int region = k0 >> 7;
        int kloc = k0 & 127;
        const float* base = (region == 0) ? d_S : (region == 1) ? d_A : x;

#pragma unroll
        for (int v = 0; v < 2; v++) {
            int id = t * 8 + v * 4;
            int r = id >> 5, c = id & 31;
            int n = n0 + r;
            float4 val = make_float4(0.f, 0.f, 0.f, 0.f);
            if (n < NUM_NODES) {
                val = ldg4(base + (size_t)n * D + kloc + c);
                if (region == 3) {
                    float dg = d_degf[n];
                    val.x *= dg; val.y *= dg; val.z *= dg; val.w *= dg;
                }
            }
            Us[r * 33 + c + 0] = val.x;
            Us[r * 33 + c + 1] = val.y;
            Us[r * 33 + c + 2] = val.z;
            Us[r * 33 + c + 3] = val.w;
        }
#pragma unroll
        for (int v = 0; v < 4; v++) {
            int id = t * 16 + v * 4;
            int r = id >> 7, c = id & 127;
            *(float4*)(Ms + r * 128 + c) = ldg4(d_Mf + (size_t)(k0 + r) * 128 + c);
        }
        __syncthreads();

#pragma unroll
        for (int kk = 0; kk < 32; kk++) {
            float u[4];
#pragma unroll
            for (int i = 0; i < 4; i++) u[i] = Us[(ng * 4 + i) * 33 + kk];
            float4 m0 = *(float4*)(Ms + kk * 128 + og * 8);
            float4 m1 = *(float4*)(Ms + kk * 128 + og * 8 + 4);
            float m[8] = {m0.x, m0.y, m0.z, m0.w, m1.x, m1.y, m1.z, m1.w};
#pragma unroll
            for (int i = 0; i < 4; i++)
#pragma unroll
                for (int jj = 0; jj < 8; jj++)
                    acc[i][jj] += u[i] * m[jj];
        }
        __syncthreads();
    }

#pragma unroll
    for (int i = 0; i < 4; i++) {
        int n = n0 + ng * 4 + i;
        if (n >= NUM_NODES) continue;
        float dg = d_degf[n];
        float o8[8];
#pragma unroll
        for (int jj = 0; jj < 8; jj++) {
            int o = og * 8 + jj;
            o8[jj] = acc[i][jj] + dg * d_cvec[o] + b2[o];
        }
        float4* outp = (float4*)(out + (size_t)n * D + og * 8);
        outp[0] = make_float4(o8[0], o8[1], o8[2], o8[3]);
        outp[1] = make_float4(o8[4], o8[5], o8[6], o8[7]);
    }
}

// ---------------- launch ----------------
extern "C" void kernel_launch(void* const* d_in, const int* in_sizes, int n_in,
                              void* d_out, int out_size) {
    const float* x  = (const float*)d_in[0];
    const void*  ei = d_in[1];
    const float* ea = (const float*)d_in[2];
    const float* W1 = (const float*)d_in[3];
    const float* b1 = (const float*)d_in[4];
    const float* W2 = (const float*)d_in[5];
    const float* b2 = (const float*)d_in[6];
    float* out = (float*)d_out;

    k_setup<<<592, 128>>>(W1, b1, W2, (const int*)ei);
    k_scatter<<<(N_EDGES + 255) / 256, 256>>>(ei);
    k_agg<<<(NUM_NODES + 3) / 4, 128>>>(x, ea);
    k_gemm<<<(NUM_NODES + 63) / 64, 256>>>(x, b2, out);
}

// round 6
// speedup vs baseline: 1.3676x; 1.0729x over previous
#include <cuda_runtime.h>
#include <cuda_bf16.h>

#define NUM_NODES 10000
#define N_EDGES   640000
#define D         128
#define BUCKET    128
#define OVF_MAX   4096

// ---------------- device scratch ----------------
__device__ float d_S[NUM_NODES * D];
__device__ float d_A[NUM_NODES * D];
__device__ int   d_cur[NUM_NODES];
__device__ float d_degf[NUM_NODES];
__device__ int2  d_perm2[NUM_NODES * BUCKET];
__device__ int3  d_ovf[OVF_MAX];
__device__ int   d_ovf_cnt;
__device__ float d_Mf[512 * D];
__device__ float d_cvec[D];
__device__ int   d_is64;

// ---------------- helpers ----------------
__device__ __forceinline__ int load_idx(const void* ei, int which, int e, int is64) {
    if (is64) {
        const long long* p = (const long long*)ei;
        return (int)__ldg(p + (size_t)which * N_EDGES + e);
    } else {
        const int* p = (const int*)ei;
        return __ldg(p + (size_t)which * N_EDGES + e);
    }
}
__device__ __forceinline__ float4 ldg4(const float* p)  { return __ldg((const float4*)p); }
__device__ __forceinline__ float4 ldcs4(const float* p) { return __ldcs((const float4*)p); }

// ---------------- K0: setup = weight fusion + dtype probe + counter zeroing ----------------
__global__ void k_setup(const float* __restrict__ W1,
                        const float* __restrict__ b1,
                        const float* __restrict__ W2,
                        const int*   __restrict__ ei_words) {
    int r = blockIdx.x, o = threadIdx.x;   // 128 threads
    if (r >= 512) {
        if (r == 512) {
            int w = ei_words[2 * o + 1];   // high words if int64
            int any = __syncthreads_or(w != 0);
            if (o == 0) { d_is64 = (any == 0) ? 1 : 0; d_ovf_cnt = 0; }
        } else {
            int i = (r - 513) * 128 + o;
            if (i < NUM_NODES) d_cur[i] = 0;
        }
        return;
    }
    __shared__ float row[D];
    if (r >= 256 && r < 384) {
        d_Mf[r * D + o] = W2[(128 + (r - 256)) * D + o];
        return;
    }
    int w1row = (r < 128) ? r : (r < 256) ? (256 + (r - 128)) : (128 + (r - 384));
    row[o] = W1[w1row * D + o];
    __syncthreads();
    float acc = 0.f;
#pragma unroll 8
    for (int h = 0; h < D; h++) acc += row[h] * __ldg(W2 + h * D + o);
    d_Mf[r * D + o] = acc;
    if (r == 0) {
        __syncthreads();
        row[o] = b1[o];
        __syncthreads();
        float c = 0.f;
#pragma unroll 8
        for (int h = 0; h < D; h++) c += row[h] * __ldg(W2 + h * D + o);
        d_cvec[o] = c;
    }
}

// ---------------- K1: single-pass bucket scatter ----------------
__global__ void k_scatter(const void* ei) {
    int is64 = d_is64;
    int e = blockIdx.x * blockDim.x + threadIdx.x;
    if (e >= N_EDGES) return;
    int dst = load_idx(ei, 1, e, is64);
    int src = load_idx(ei, 0, e, is64);
    int pos = atomicAdd(&d_cur[dst], 1);
    if (pos < BUCKET) {
        d_perm2[(dst << 7) + pos] = make_int2(e, src);
    } else {
        int o = atomicAdd(&d_ovf_cnt, 1);
        if (o < OVF_MAX) d_ovf[o] = make_int3(dst, e, src);
    }
}

// ---------------- K2: atomic-free segment sums (R5 known-good) ----------------
__global__ void k_agg(const float* __restrict__ x, const float* __restrict__ ea) {
    int n = blockIdx.x * 4 + (threadIdx.x >> 5);
    if (n >= NUM_NODES) return;
    int lane = threadIdx.x & 31;
    int deg = d_cur[n];
    if (lane == 0) d_degf[n] = (float)deg;
    int cnt = min(deg, BUCKET);
    const int2* bucket = d_perm2 + ((size_t)n << 7);

    float4 aS = make_float4(0.f, 0.f, 0.f, 0.f);
    float4 aA = make_float4(0.f, 0.f, 0.f, 0.f);

    int j = 0;
    for (; j + 4 <= cnt; j += 4) {
        int2 p0 = __ldg(bucket + j + 0);
        int2 p1 = __ldg(bucket + j + 1);
        int2 p2 = __ldg(bucket + j + 2);
        int2 p3 = __ldg(bucket + j + 3);
        float4 x0 = ldg4(x + (size_t)p0.y * D + lane * 4);
        float4 x1 = ldg4(x + (size_t)p1.y * D + lane * 4);
        float4 x2 = ldg4(x + (size_t)p2.y * D + lane * 4);
        float4 x3 = ldg4(x + (size_t)p3.y * D + lane * 4);
        float4 a0 = ldcs4(ea + (size_t)p0.x * D + lane * 4);
        float4 a1 = ldcs4(ea + (size_t)p1.x * D + lane * 4);
        float4 a2 = ldcs4(ea + (size_t)p2.x * D + lane * 4);
        float4 a3 = ldcs4(ea + (size_t)p3.x * D + lane * 4);
        aS.x += (x0.x + x1.x) + (x2.x + x3.x);
        aS.y += (x0.y + x1.y) + (x2.y + x3.y);
        aS.z += (x0.z + x1.z) + (x2.z + x3.z);
        aS.w += (x0.w + x1.w) + (x2.w + x3.w);
        aA.x += (a0.x + a1.x) + (a2.x + a3.x);
        aA.y += (a0.y + a1.y) + (a2.y + a3.y);
        aA.z += (a0.z + a1.z) + (a2.z + a3.z);
        aA.w += (a0.w + a1.w) + (a2.w + a3.w);
    }
    for (; j < cnt; j++) {
        int2 p = __ldg(bucket + j);
        float4 xv = ldg4(x + (size_t)p.y * D + lane * 4);
        float4 av = ldcs4(ea + (size_t)p.x * D + lane * 4);
        aS.x += xv.x; aS.y += xv.y; aS.z += xv.z; aS.w += xv.w;
        aA.x += av.x; aA.y += av.y; aA.z += av.z; aA.w += av.w;
    }

    if (deg > BUCKET) {
        int cnt_o = d_ovf_cnt;
        if (cnt_o > OVF_MAX) cnt_o = OVF_MAX;
        for (int i = 0; i < cnt_o; i++) {
            int3 v = d_ovf[i];
            if (v.x == n) {
                float4 xv = ldg4(x + (size_t)v.z * D + lane * 4);
                float4 av = ldg4(ea + (size_t)v.y * D + lane * 4);
                aS.x += xv.x; aS.y += xv.y; aS.z += xv.z; aS.w += xv.w;
                aA.x += av.x; aA.y += av.y; aA.z += av.z; aA.w += av.w;
            }
        }
    }

    *(float4*)(d_S + (size_t)n * D + lane * 4) = aS;
    *(float4*)(d_A + (size_t)n * D + lane * 4) = aA;
}

// ---------------- K3: fused node GEMM — warp-per-output-group layout ----------------
// Block: 32 nodes x 128 outs, 256 threads (8 warps).
// Warp w owns outputs [16w, 16w+16); lane owns one node.
// Per kk: 1 conflict-free scalar U load + 4 broadcast float4 M loads -> 16 FMAs.
__global__ void __launch_bounds__(256)
k_gemm(const float* __restrict__ x,
       const float* __restrict__ b2,
       float* __restrict__ out) {
    __shared__ float Us[32 * 33];
    __shared__ float Ms[32 * 128];
    int t = threadIdx.x;
    int w = t >> 5;           // output group
    int lane = t & 31;        // node within tile
    int n0 = blockIdx.x * 32;
    int n = n0 + lane;

    float acc[16];
#pragma unroll
    for (int j = 0; j < 16; j++) acc[j] = 0.f;

    for (int k0 = 0; k0 < 512; k0 += 32) {
        int region = k0 >> 7;
        int kloc = k0 & 127;
        const float* base = (region == 0) ? d_S : (region == 1) ? d_A : x;

        // U tile: 32x32 floats, one float4 per thread
        {
            int r = t >> 3, c = (t & 7) * 4;
            int nn = n0 + r;
            float4 val = make_float4(0.f, 0.f, 0.f, 0.f);
            if (nn < NUM_NODES) {
                val = ldg4(base + (size_t)nn * D + kloc + c);
                if (region == 3) {
                    float dg = d_degf[nn];
                    val.x *= dg; val.y *= dg; val.z *= dg; val.w *= dg;
                }
            }
            Us[r * 33 + c + 0] = val.x;
            Us[r * 33 + c + 1] = val.y;
            Us[r * 33 + c + 2] = val.z;
            Us[r * 33 + c + 3] = val.w;
        }
        // M tile: 32x128 floats, 4 float4 per thread
#pragma unroll
        for (int v = 0; v < 4; v++) {
            int id = t * 16 + v * 4;
            int r = id >> 7, c = id & 127;
            *(float4*)(Ms + r * 128 + c) = ldg4(d_Mf + (size_t)(k0 + r) * 128 + c);
        }
        __syncthreads();

#pragma unroll
        for (int kk = 0; kk < 32; kk++) {
            float u = Us[lane * 33 + kk];                 // bank = (lane+kk)&31: conflict-free
            const float4* mrow = (const float4*)(Ms + kk * 128 + w * 16);
            float4 m0 = mrow[0];                          // warp-broadcast
            float4 m1 = mrow[1];
            float4 m2 = mrow[2];
            float4 m3 = mrow[3];
            acc[ 0] += u * m0.x; acc[ 1] += u * m0.y; acc[ 2] += u * m0.z; acc[ 3] += u * m0.w;
            acc[ 4] += u * m1.x; acc[ 5] += u * m1.y; acc[ 6] += u * m1.z; acc[ 7] += u * m1.w;
            acc[ 8] += u * m2.x; acc[ 9] += u * m2.y; acc[10] += u * m2.z; acc[11] += u * m2.w;
            acc[12] += u * m3.x; acc[13] += u * m3.y; acc[14] += u * m3.z; acc[15] += u * m3.w;
        }
        __syncthreads();
    }

    if (n < NUM_NODES) {
        float dg = d_degf[n];
        float o16[16];
#pragma unroll
        for (int j = 0; j < 16; j++) {
            int o = w * 16 + j;
            o16[j] = acc[j] + dg * d_cvec[o] + b2[o];
        }
        float4* outp = (float4*)(out + (size_t)n * D + w * 16);
        outp[0] = make_float4(o16[ 0], o16[ 1], o16[ 2], o16[ 3]);
        outp[1] = make_float4(o16[ 4], o16[ 5], o16[ 6], o16[ 7]);
        outp[2] = make_float4(o16[ 8], o16[ 9], o16[10], o16[11]);
        outp[3] = make_float4(o16[12], o16[13], o16[14], o16[15]);
    }
}

// ---------------- launch ----------------
extern "C" void kernel_launch(void* const* d_in, const int* in_sizes, int n_in,
                              void* d_out, int out_size) {
    const float* x  = (const float*)d_in[0];
    const void*  ei = d_in[1];
    const float* ea = (const float*)d_in[2];
    const float* W1 = (const float*)d_in[3];
    const float* b1 = (const float*)d_in[4];
    const float* W2 = (const float*)d_in[5];
    const float* b2 = (const float*)d_in[6];
    float* out = (float*)d_out;

    k_setup<<<592, 128>>>(W1, b1, W2, (const int*)ei);
    k_scatter<<<(N_EDGES + 255) / 256, 256>>>(ei);
    k_agg<<<(NUM_NODES + 3) / 4, 128>>>(x, ea);
    k_gemm<<<(NUM_NODES + 31) / 32, 256>>>(x, b2, out);
}